// round 14
// baseline (speedup 1.0000x reference)
#include <cuda_runtime.h>

// XY model log-density: out[s] = sum_i cos(x[up(i)] - x[i]) + cos(x[right(i)] - x[i])
// 64x64 lattice (4096 sites), 16384 samples, BETA = 1.
//
// R14: R13 (chained chunks, 41.7us, DRAM 84%) + SECOND bond offloaded to the
// FMA pipe. MUFU est. ~64% busy co-binds with DRAM; moving 2/8 bonds to
// cos_poly drops it to ~55% (fma 39% -> ~50%), freeing issue latency so
// chain loads launch sooner.

#define LATTICE 4096
#define THREADS 256

// FMA-pipe cos for d in (-2pi,2pi): half-angle + even Taylor, err <= 4e-6.
__device__ __forceinline__ float cos_poly(float d)
{
    const float y = 0.5f * d;
    const float u = y * y;
    float p = -1.1470746e-11f;
    p = fmaf(p, u,  2.0876757e-9f);
    p = fmaf(p, u, -2.7557319e-7f);
    p = fmaf(p, u,  2.4801587e-5f);
    p = fmaf(p, u, -1.3888889e-3f);
    p = fmaf(p, u,  4.1666668e-2f);
    p = fmaf(p, u, -0.5f);
    p = fmaf(p, u,  1.0f);              // p = cos(y)
    return fmaf(p + p, p, -1.0f);       // 2p^2 - 1
}

__global__ __launch_bounds__(THREADS) void xy_hamiltonian_kernel(
    const float* __restrict__ state,
    float* __restrict__ out)
{
    __shared__ float warp_sums[THREADS / 32];

    const int tid  = threadIdx.x;
    const int lane = tid & 31;
    const float4* __restrict__ rp4 =
        reinterpret_cast<const float4*>(state + (size_t)blockIdx.x * LATTICE);

    // Chain start: chunks with (m mod 64) < 16. Lanes 0-15 of a warp cover
    // 16 consecutive chunks of one lattice row; lanes 16-31 the next group.
    const int start = ((tid >> 4) << 6) + (tid & 15);

    // Right-neighbor source lane: within each 16-lane group, lane L's
    // boundary right-neighbor is lane L+1's cur.x, wrapping at col 63.
    const int src_lane = (lane & ~15) | ((lane + 1) & 15);

    float4 cur = __ldcs(&rp4[start]);

    float acc  = 0.0f;   // MUFU-side accumulator
    float accp = 0.0f;   // poly-side accumulator (independent chain)
    #pragma unroll
    for (int j = 0; j < 4; j++) {
        // Up-neighbor chunk = next chunk in this thread's chain.
        const float4 nxt = __ldcs(&rp4[(start + 16 * (j + 1)) & (LATTICE/4 - 1)]);
        const float xr3 = __shfl_sync(0xffffffffu, cur.x, src_lane);

        acc  += __cosf(nxt.x - cur.x);     // up bonds (MUFU)
        acc  += __cosf(nxt.y - cur.y);
        acc  += __cosf(nxt.z - cur.z);
        acc  += __cosf(nxt.w - cur.w);
        acc  += __cosf(cur.y - cur.x);     // right bonds
        accp += cos_poly(cur.z - cur.y);   // FMA-pipe bond #1
        accp += cos_poly(cur.w - cur.z);   // FMA-pipe bond #2
        acc  += __cosf(xr3   - cur.w);

        cur = nxt;
    }
    acc += accp;

    // Warp reduce
    #pragma unroll
    for (int o = 16; o > 0; o >>= 1)
        acc += __shfl_down_sync(0xffffffffu, acc, o);
    if (lane == 0)
        warp_sums[tid >> 5] = acc;
    __syncthreads();

    // Final reduce across 8 warps
    if (tid < 8) {
        float v = warp_sums[tid];
        #pragma unroll
        for (int o = 4; o > 0; o >>= 1)
            v += __shfl_down_sync(0x000000ffu, v, o);
        if (tid == 0)
            out[blockIdx.x] = v;
    }
}

extern "C" void kernel_launch(void* const* d_in, const int* in_sizes, int n_in,
                              void* d_out, int out_size)
{
    const float* state = (const float*)d_in[0];
    // d_in[1] (shift table, int64) is reproduced arithmetically in-kernel.
    float* out = (float*)d_out;

    const int n_samples = in_sizes[0] / LATTICE;  // 16384
    xy_hamiltonian_kernel<<<n_samples, THREADS>>>(state, out);
}

// round 15
// speedup vs baseline: 1.0556x; 1.0556x over previous
#include <cuda_runtime.h>

// XY model log-density: out[s] = sum_i cos(x[up(i)] - x[i]) + cos(x[right(i)] - x[i])
// 64x64 lattice (4096 sites), 16384 samples, BETA = 1.
//
// R15: R13 (chained chunks, best 41.7us) with the FMA-poly bond reverted to
// MUFU __cosf. Bracket test {0,1,2} poly bonds: 2 regressed via issue
// pressure (71%); 0 minimizes issued instructions (~-9%/iter), maximizing
// issue slack for the chain loads.
//
// Structure: thread t owns chunk chain {start, +16, +32, +48} (stride = one
// lattice row), so each chunk's up-neighbor IS the next chain chunk:
// 5 loads/thread instead of 8. start = (tid>>4)*64 + (tid&15) keeps every
// warp LDG on 4x128B lines. Right bonds from registers + 1 SHFL (wrap-aware).

#define LATTICE 4096
#define THREADS 256

__global__ __launch_bounds__(THREADS) void xy_hamiltonian_kernel(
    const float* __restrict__ state,
    float* __restrict__ out)
{
    __shared__ float warp_sums[THREADS / 32];

    const int tid  = threadIdx.x;
    const int lane = tid & 31;
    const float4* __restrict__ rp4 =
        reinterpret_cast<const float4*>(state + (size_t)blockIdx.x * LATTICE);

    // Chain start: chunks with (m mod 64) < 16. Lanes 0-15 of a warp cover
    // 16 consecutive chunks of one lattice row; lanes 16-31 the next group.
    const int start = ((tid >> 4) << 6) + (tid & 15);

    // Right-neighbor source lane: within each 16-lane group, lane L's
    // boundary right-neighbor is lane L+1's cur.x, wrapping at col 63.
    const int src_lane = (lane & ~15) | ((lane + 1) & 15);

    float4 cur = __ldcs(&rp4[start]);

    float acc = 0.0f;
    #pragma unroll
    for (int j = 0; j < 4; j++) {
        // Up-neighbor chunk = next chunk in this thread's chain.
        const float4 nxt = __ldcs(&rp4[(start + 16 * (j + 1)) & (LATTICE/4 - 1)]);
        const float xr3 = __shfl_sync(0xffffffffu, cur.x, src_lane);

        acc += __cosf(nxt.x - cur.x);   // up bonds
        acc += __cosf(nxt.y - cur.y);
        acc += __cosf(nxt.z - cur.z);
        acc += __cosf(nxt.w - cur.w);
        acc += __cosf(cur.y - cur.x);   // right bonds
        acc += __cosf(cur.z - cur.y);
        acc += __cosf(cur.w - cur.z);
        acc += __cosf(xr3   - cur.w);

        cur = nxt;
    }

    // Warp reduce
    #pragma unroll
    for (int o = 16; o > 0; o >>= 1)
        acc += __shfl_down_sync(0xffffffffu, acc, o);
    if (lane == 0)
        warp_sums[tid >> 5] = acc;
    __syncthreads();

    // Final reduce across 8 warps
    if (tid < 8) {
        float v = warp_sums[tid];
        #pragma unroll
        for (int o = 4; o > 0; o >>= 1)
            v += __shfl_down_sync(0x000000ffu, v, o);
        if (tid == 0)
            out[blockIdx.x] = v;
    }
}

extern "C" void kernel_launch(void* const* d_in, const int* in_sizes, int n_in,
                              void* d_out, int out_size)
{
    const float* state = (const float*)d_in[0];
    // d_in[1] (shift table, int64) is reproduced arithmetically in-kernel.
    float* out = (float*)d_out;

    const int n_samples = in_sizes[0] / LATTICE;  // 16384
    xy_hamiltonian_kernel<<<n_samples, THREADS>>>(state, out);
}